// round 8
// baseline (speedup 1.0000x reference)
#include <cuda_runtime.h>
#include <cuda_bf16.h>
#include <cstdint>

#define Bsz   128
#define Tlen  1024
#define Isz   512
#define Hsz   512
#define NCTA  128
#define TPB   288      // 8 compute warps (4 kg x 2 ng) + 1 producer warp
#define PTPB  256
#define NKT   16
#define NSTG  8        // 2 stages per kg

// ---------------- device scratch ----------------
__device__ __align__(1024) char g_xs_hi[(size_t)Tlen * 2 * 8 * 8192];
__device__ __align__(1024) char g_xs_lo[(size_t)Tlen * 2 * 8 * 8192];
__device__ __align__(1024) char g_hs_hi[2 * 2 * 8 * 8192];
__device__ __align__(1024) char g_hs_lo[2 * 2 * 8 * 8192];
__device__ __nv_bfloat16 g_w_hi[(size_t)2048 * 1024];
__device__ __nv_bfloat16 g_w_lo[(size_t)2048 * 1024];
__device__ volatile unsigned g_flags[NCTA];
__device__ volatile unsigned g_release;

// ---------------- helpers ----------------
__device__ __forceinline__ uint32_t smem_u32(const void* p) {
    uint32_t a;
    asm("{ .reg .u64 t; cvta.to.shared.u64 t, %1; cvt.u32.u64 %0, t; }" : "=r"(a) : "l"(p));
    return a;
}
__device__ __forceinline__ void cpa16(uint32_t dst, const void* src) {
    asm volatile("cp.async.cg.shared.global [%0], [%1], 16;\n" :: "r"(dst), "l"(src));
}
#define CP_COMMIT()  asm volatile("cp.async.commit_group;\n")
#define CP_WAIT(n)   asm volatile("cp.async.wait_group %0;\n" :: "n"(n))

__device__ __forceinline__ void bulk_ld(uint32_t dst, const void* src, uint32_t bytes,
                                        uint32_t mbar) {
    asm volatile(
        "cp.async.bulk.shared::cluster.global.mbarrier::complete_tx::bytes [%0], [%1], %2, [%3];"
        :: "r"(dst), "l"(src), "r"(bytes), "r"(mbar) : "memory");
}
__device__ __forceinline__ void mbar_init(uint32_t m, uint32_t cnt) {
    asm volatile("mbarrier.init.shared.b64 [%0], %1;" :: "r"(m), "r"(cnt) : "memory");
}
__device__ __forceinline__ void mbar_expect(uint32_t m, uint32_t bytes) {
    asm volatile("mbarrier.arrive.expect_tx.shared.b64 _, [%0], %1;"
                 :: "r"(m), "r"(bytes) : "memory");
}
__device__ __forceinline__ void mbar_arrive(uint32_t m) {
    asm volatile("mbarrier.arrive.shared.b64 _, [%0];" :: "r"(m) : "memory");
}
__device__ __forceinline__ void mbar_wait(uint32_t m, uint32_t parity) {
    uint32_t done;
    asm volatile("{\n\t.reg .pred p;\n\t"
        "mbarrier.try_wait.parity.acquire.cta.shared::cta.b64 p, [%1], %2;\n\t"
        "selp.b32 %0, 1, 0, p;\n\t}"
        : "=r"(done) : "r"(m), "r"(parity) : "memory");
    if (!done) {
        asm volatile("{\n\t.reg .pred P1;\n\t"
            "WL_%=:\n\t"
            "mbarrier.try_wait.parity.acquire.cta.shared::cta.b64 P1, [%0], %1, 0x989680;\n\t"
            "@P1 bra.uni WD_%=;\n\t"
            "bra.uni WL_%=;\n\t"
            "WD_%=:\n\t}" :: "r"(m), "r"(parity) : "memory");
    }
}

#define LDSM4(r, a) \
    asm volatile("ldmatrix.sync.aligned.m8n8.x4.shared.b16 {%0,%1,%2,%3},[%4];" \
        : "=r"((r)[0]),"=r"((r)[1]),"=r"((r)[2]),"=r"((r)[3]) : "r"(a))
#define LDSM2(r, a) \
    asm volatile("ldmatrix.sync.aligned.m8n8.x2.shared.b16 {%0,%1},[%2];" \
        : "=r"((r)[0]),"=r"((r)[1]) : "r"(a))
#define MMA16816(d, a, b) \
    asm volatile("mma.sync.aligned.m16n8k16.row.col.f32.bf16.bf16.f32 " \
        "{%0,%1,%2,%3},{%4,%5,%6,%7},{%8,%9},{%0,%1,%2,%3};" \
        : "+f"((d)[0]),"+f"((d)[1]),"+f"((d)[2]),"+f"((d)[3]) \
        : "r"((a)[0]),"r"((a)[1]),"r"((a)[2]),"r"((a)[3]),"r"((b)[0]),"r"((b)[1]))

__device__ __forceinline__ float sigmoidf_(float x) { return 1.f / (1.f + expf(-x)); }

// ---------------- smem layout (bytes) ----------------
// Phase 0 (init): bias/mbars @0..1024, ws_hi @1024, ws_lo @67072 (ends 133120)
// Phase 1 (steady, overlays ws): ring 8x16384 @1024 (ends 132096),
//                                zpart 4x64x144B @132096 (ends 168960)
#define BS_OFF     0
#define MB_FULL    128          // 8 x 8B
#define MB_EMPTY   192          // 8 x 8B
#define WS_HI      1024
#define WS_LO      67072
#define WS_STRIDE  2064
#define RING_OFF   1024
#define A_BUF      16384
#define A_LOH      8192
#define ZP_OFF     132096
#define ZP_KG      9216         // 64 rows * 144B
#define ZP_ROW     144
#define SMEM_TOTAL 168960

// ---------------- prologue kernels ----------------
__global__ void init_kernel() {
    int idx = blockIdx.x * blockDim.x + threadIdx.x;
    int stride = gridDim.x * blockDim.x;
    int* hh = (int*)g_hs_hi;
    int* hl = (int*)g_hs_lo;
    for (int i = idx; i < (2 * 2 * 8 * 8192) / 4; i += stride) { hh[i] = 0; hl[i] = 0; }
    if (idx < NCTA) g_flags[idx] = 0u;
    if (idx == 0)   g_release   = 0u;
}

__global__ void prep_w(const float* __restrict__ Wk, const float* __restrict__ Rk) {
    __shared__ float tile[32][33];
    int gt = blockIdx.x * 32, kt = blockIdx.y * 32;
    int tid = threadIdx.x;
    for (int i = tid; i < 1024; i += PTPB) {
        int kk = i >> 5, gg = i & 31;
        int k = kt + kk, g = gt + gg;
        tile[kk][gg] = (k < 512) ? Wk[(size_t)k * 2048 + g]
                                 : Rk[(size_t)(k - 512) * 2048 + g];
    }
    __syncthreads();
    for (int i = tid; i < 1024; i += PTPB) {
        int gg = i >> 5, kk = i & 31;
        float v = tile[kk][gg];
        __nv_bfloat16 hi = __float2bfloat16(v);
        __nv_bfloat16 lo = __float2bfloat16(v - __bfloat162float(hi));
        size_t o = (size_t)(gt + gg) * 1024 + (size_t)(kt + kk);
        g_w_hi[o] = hi; g_w_lo[o] = lo;
    }
}

__global__ void prep_x(const float* __restrict__ x) {
    int t = blockIdx.x, b = blockIdx.y;
    int bg = b >> 6, r = b & 63;
    const float* src = x + ((size_t)b * Tlen + t) * Isz;
    size_t tbase = (((size_t)t * 2 + bg) * 8) * 8192;
    for (int k = threadIdx.x; k < Isz; k += blockDim.x) {
        float v = src[k];
        __nv_bfloat16 hi = __float2bfloat16(v);
        __nv_bfloat16 lo = __float2bfloat16(v - __bfloat162float(hi));
        int kt = k >> 6, kk = k & 63;
        size_t off = tbase + (size_t)kt * 8192 + r * 128 + (((kk * 2) ^ ((r & 7) << 4)));
        *(__nv_bfloat16*)(g_xs_hi + off) = hi;
        *(__nv_bfloat16*)(g_xs_lo + off) = lo;
    }
}

// ---------------- main persistent kernel ----------------
__global__ void __launch_bounds__(TPB, 1) lstm_mma(const float* __restrict__ bias,
                                                   float* __restrict__ out) {
    extern __shared__ char smem[];
    const uint32_t sbase = smem_u32(smem);
    float* bs = (float*)(smem + BS_OFF);

    const int tid = threadIdx.x, wid = tid >> 5, lid = tid & 31;
    const int cta = blockIdx.x;
    const int cg  = cta & 63;        // 8 h-cols
    const int bg  = cta >> 6;        // 64 batch rows
    const int kg  = wid >> 1;        // K-group (K slice of 256)
    const int ng  = wid & 1;         // N-group (16 n-cols)

    // ---- phase 0: weights into smem (transient) ----
    for (int i = tid; i < 32 * 128 * 2; i += TPB) {
        int half = i >= 32 * 128;
        int j = half ? i - 32 * 128 : i;
        int c = j >> 7, ch = j & 127;
        int g = (c & 3) * 512 + cg * 8 + (c >> 2);
        const __nv_bfloat16* src = (half ? g_w_lo : g_w_hi) + (size_t)g * 1024 + ch * 8;
        cpa16(sbase + (half ? WS_LO : WS_HI) + c * WS_STRIDE + ch * 16, src);
    }
    CP_COMMIT();
    if (tid < 32)
        bs[tid] = bias[(tid & 3) * 512 + cg * 8 + (tid >> 2)];
    if (tid == 0) {
        #pragma unroll
        for (int s = 0; s < NSTG; s++) {
            mbar_init(sbase + MB_FULL  + s * 8, 1);
            mbar_init(sbase + MB_EMPTY + s * 8, 2);
        }
    }
    CP_WAIT(0);
    __syncthreads();

    // ---- extract this warp's B fragments into registers (held forever) ----
    uint32_t Bh[16][2][2], Bl[16][2][2];
    if (wid < 8) {
        #pragma unroll
        for (int kc = 0; kc < 16; kc++) {
            #pragma unroll
            for (int nt = 0; nt < 2; nt++) {
                uint32_t a = sbase + WS_HI
                           + (ng * 16 + nt * 8 + (lid & 7)) * WS_STRIDE
                           + ((lid >> 3) & 1) * 16
                           + kg * 512 + kc * 32;
                LDSM2(Bh[kc][nt], a);
                LDSM2(Bl[kc][nt], a + (WS_LO - WS_HI));
            }
        }
    }
    __syncthreads();   // ws region dead; ring/zpart overlay it

    // stage map: stage(kt) = (kt>>2)*2 + (kt&1); u(t,kt) = 2t + ((kt&3)>>1)
    auto issue_tile = [&](int t, int kt) {
        const int s = ((kt >> 2) << 1) | (kt & 1);
        const int u = t * 2 + ((kt & 3) >> 1);
        mbar_wait(sbase + MB_EMPTY + s * 8, (u & 1) ^ 1);
        const char *sh, *sl;
        if (kt < 8) {
            size_t o = (((size_t)t * 2 + bg) * 8 + kt) * 8192;
            sh = g_xs_hi + o; sl = g_xs_lo + o;
        } else {
            size_t o = (((size_t)(t & 1) * 2 + bg) * 8 + (kt - 8)) * 8192;
            sh = g_hs_hi + o; sl = g_hs_lo + o;
        }
        const uint32_t abuf = sbase + RING_OFF + s * A_BUF;
        mbar_expect(sbase + MB_FULL + s * 8, 16384);
        bulk_ld(abuf,         sh, 8192, sbase + MB_FULL + s * 8);
        bulk_ld(abuf + A_LOH, sl, 8192, sbase + MB_FULL + s * 8);
    };

    // prime: first 2 tiles of kg0 and kg1 (x tiles of step 0)
    if (wid == 8 && lid == 0) {
        issue_tile(0, 0); issue_tile(0, 1); issue_tile(0, 4); issue_tile(0, 5);
    }

    // compute-warp A addressing
    const uint32_t a_row   = (lid & 15) * 128;
    const uint32_t a_cmask = (lid & 7) << 4;
    const uint32_t a_chi   = (lid >> 4) * 16;

    float creg[2] = {0.f, 0.f};

    for (int t = 0; t < Tlen; t++) {
        if (wid == 8) {
            // ---------------- producer warp ----------------
            if (lid == 0) {
                issue_tile(t, 2); issue_tile(t, 6); issue_tile(t, 3); issue_tile(t, 7);
                if (t > 0) {
                    while (g_release < (unsigned)t) { }
                    __threadfence();
                }
                issue_tile(t, 8);  issue_tile(t, 12); issue_tile(t, 9);  issue_tile(t, 13);
                issue_tile(t, 10); issue_tile(t, 14); issue_tile(t, 11); issue_tile(t, 15);
                if (t + 1 < Tlen) {
                    issue_tile(t + 1, 0); issue_tile(t + 1, 1);
                    issue_tile(t + 1, 4); issue_tile(t + 1, 5);
                }
            }
        } else {
            // ---------------- compute warps: own K-slice ----------------
            float acc[4][2][4];
            #pragma unroll
            for (int mt = 0; mt < 4; mt++)
                #pragma unroll
                for (int nt = 0; nt < 2; nt++)
                    #pragma unroll
                    for (int j = 0; j < 4; j++) acc[mt][nt][j] = 0.f;

            #pragma unroll
            for (int i = 0; i < 4; i++) {
                const int s = (kg << 1) | (i & 1);
                const int u = t * 2 + (i >> 1);
                mbar_wait(sbase + MB_FULL + s * 8, u & 1);

                const uint32_t abuf = sbase + RING_OFF + s * A_BUF;
                #pragma unroll
                for (int ks = 0; ks < 4; ks++) {
                    const uint32_t col = ((uint32_t)(ks * 32) + a_chi) ^ a_cmask;
                    #pragma unroll
                    for (int mt = 0; mt < 4; mt++) {
                        uint32_t ah[4], al[4];
                        LDSM4(ah, abuf + mt * 2048 + a_row + col);
                        LDSM4(al, abuf + A_LOH + mt * 2048 + a_row + col);
                        #pragma unroll
                        for (int nt = 0; nt < 2; nt++) {
                            MMA16816(acc[mt][nt], ah, Bh[i * 4 + ks][nt]);
                            MMA16816(acc[mt][nt], ah, Bl[i * 4 + ks][nt]);
                            MMA16816(acc[mt][nt], al, Bh[i * 4 + ks][nt]);
                        }
                    }
                }
                if (lid == 0) mbar_arrive(sbase + MB_EMPTY + s * 8);
            }

            // store fp32 partials to zpart[kg]
            #pragma unroll
            for (int mt = 0; mt < 4; mt++) {
                #pragma unroll
                for (int nt = 0; nt < 2; nt++) {
                    const int r0 = mt * 16 + (lid >> 2);
                    const int c0 = ng * 16 + nt * 8 + (lid & 3) * 2;
                    char* base = smem + ZP_OFF + kg * ZP_KG + c0 * 4;
                    *(float2*)(base + r0 * ZP_ROW) =
                        make_float2(acc[mt][nt][0], acc[mt][nt][1]);
                    *(float2*)(base + (r0 + 8) * ZP_ROW) =
                        make_float2(acc[mt][nt][2], acc[mt][nt][3]);
                }
            }
        }

        __syncthreads();    // partials visible

        // ---- reduce across K-groups + gates (compute threads, 2 elems each) ----
        if (wid < 8) {
            const int par2 = (t + 1) & 1;
            #pragma unroll
            for (int e = 0; e < 2; e++) {
                const int el = tid * 2 + e;          // 0..511
                const int b  = el >> 3;              // 0..63
                const int hc = el & 7;               // 0..7
                float4 z = make_float4(0.f, 0.f, 0.f, 0.f);
                #pragma unroll
                for (int k4 = 0; k4 < 4; k4++) {
                    float4 p = *(const float4*)(smem + ZP_OFF + k4 * ZP_KG
                                                + b * ZP_ROW + hc * 16);
                    z.x += p.x; z.y += p.y; z.z += p.z; z.w += p.w;
                }
                float zi = z.x + bs[hc * 4 + 0];
                float zf = z.y + bs[hc * 4 + 1];
                float zg = z.z + bs[hc * 4 + 2];
                float zo = z.w + bs[hc * 4 + 3];
                float ii = sigmoidf_(zi);
                float ff = sigmoidf_(zf);
                float gg = tanhf(zg);
                float oo = sigmoidf_(zo);
                float cn = tanhf(ff * creg[e] + ii * gg);
                float hn = oo * cn;
                creg[e] = cn;

                const int b_glob = bg * 64 + b;
                const int hcol   = cg * 8 + hc;
                out[(size_t)b_glob * (Tlen * Hsz) + (size_t)t * Hsz + hcol] = hn;

                __nv_bfloat16 hh = __float2bfloat16(hn);
                size_t off = (((size_t)par2 * 2 + bg) * 8 + (hcol >> 6)) * 8192
                           + b * 128 + ((((hcol & 63) * 2) ^ ((b & 7) << 4)));
                *(__nv_bfloat16*)(g_hs_hi + off) = hh;
                *(__nv_bfloat16*)(g_hs_lo + off) =
                    __float2bfloat16(hn - __bfloat162float(hh));
            }
            __threadfence();
        }

        __syncthreads();    // h published

        // ---- grid barrier (producer warp only) ----
        if (t < Tlen - 1 && wid == 8) {
            unsigned gen = (unsigned)(t + 1);
            if (cta == 0) {
                if (lid == 0) g_flags[0] = gen;
                bool done;
                do {
                    done = true;
                    #pragma unroll
                    for (int j = 0; j < NCTA / 32; j++)
                        if (g_flags[lid + 32 * j] < gen) done = false;
                } while (!__all_sync(0xffffffffu, done));
                if (lid == 0) { __threadfence(); g_release = gen; }
            } else if (lid == 0) {
                g_flags[cta] = gen;
            }
        }
    }
}

// ---------------- launch ----------------
extern "C" void kernel_launch(void* const* d_in, const int* in_sizes, int n_in,
                              void* d_out, int out_size) {
    const float* x    = (const float*)d_in[0];
    const float* Wk   = (const float*)d_in[1];
    const float* Rk   = (const float*)d_in[2];
    const float* bias = (const float*)d_in[3];
    float* out = (float*)d_out;

    cudaFuncSetAttribute(lstm_mma, cudaFuncAttributeMaxDynamicSharedMemorySize, SMEM_TOTAL);

    init_kernel<<<64, PTPB>>>();
    prep_w<<<dim3(64, 32), PTPB>>>(Wk, Rk);
    prep_x<<<dim3(Tlen, Bsz), 128>>>(x);
    lstm_mma<<<NCTA, TPB, SMEM_TOTAL>>>(bias, out);
}

// round 9
// speedup vs baseline: 1.2401x; 1.2401x over previous
#include <cuda_runtime.h>
#include <cuda_bf16.h>
#include <cstdint>

#define Bsz   128
#define Tlen  1024
#define Isz   512
#define Hsz   512
#define NCTA  128
#define TPB   288      // 8 compute warps (4 kg x 2 ng) + 1 producer warp
#define PTPB  256
#define NKT   16
#define NSTG  8        // 2 stages per kg

// ---------------- device scratch ----------------
__device__ __align__(1024) char g_xs_hi[(size_t)Tlen * 2 * 8 * 8192];
__device__ __align__(1024) char g_xs_lo[(size_t)Tlen * 2 * 8 * 8192];
__device__ __align__(1024) char g_hs_hi[2 * 2 * 8 * 8192];
__device__ __align__(1024) char g_hs_lo[2 * 2 * 8 * 8192];
__device__ __nv_bfloat16 g_w_hi[(size_t)2048 * 1024];
__device__ __nv_bfloat16 g_w_lo[(size_t)2048 * 1024];
__device__ volatile unsigned g_flags[NCTA];
__device__ volatile unsigned g_release;

// ---------------- helpers ----------------
__device__ __forceinline__ uint32_t smem_u32(const void* p) {
    uint32_t a;
    asm("{ .reg .u64 t; cvta.to.shared.u64 t, %1; cvt.u32.u64 %0, t; }" : "=r"(a) : "l"(p));
    return a;
}
__device__ __forceinline__ void cpa16(uint32_t dst, const void* src) {
    asm volatile("cp.async.cg.shared.global [%0], [%1], 16;\n" :: "r"(dst), "l"(src));
}
#define CP_COMMIT()  asm volatile("cp.async.commit_group;\n")
#define CP_WAIT(n)   asm volatile("cp.async.wait_group %0;\n" :: "n"(n))

__device__ __forceinline__ void bulk_ld(uint32_t dst, const void* src, uint32_t bytes,
                                        uint32_t mbar) {
    asm volatile(
        "cp.async.bulk.shared::cluster.global.mbarrier::complete_tx::bytes [%0], [%1], %2, [%3];"
        :: "r"(dst), "l"(src), "r"(bytes), "r"(mbar) : "memory");
}
__device__ __forceinline__ void mbar_init(uint32_t m, uint32_t cnt) {
    asm volatile("mbarrier.init.shared.b64 [%0], %1;" :: "r"(m), "r"(cnt) : "memory");
}
__device__ __forceinline__ void mbar_expect(uint32_t m, uint32_t bytes) {
    asm volatile("mbarrier.arrive.expect_tx.shared.b64 _, [%0], %1;"
                 :: "r"(m), "r"(bytes) : "memory");
}
__device__ __forceinline__ void mbar_arrive(uint32_t m) {
    asm volatile("mbarrier.arrive.shared.b64 _, [%0];" :: "r"(m) : "memory");
}
__device__ __forceinline__ void mbar_wait(uint32_t m, uint32_t parity) {
    uint32_t done;
    asm volatile("{\n\t.reg .pred p;\n\t"
        "mbarrier.try_wait.parity.acquire.cta.shared::cta.b64 p, [%1], %2;\n\t"
        "selp.b32 %0, 1, 0, p;\n\t}"
        : "=r"(done) : "r"(m), "r"(parity) : "memory");
    if (!done) {
        asm volatile("{\n\t.reg .pred P1;\n\t"
            "WL_%=:\n\t"
            "mbarrier.try_wait.parity.acquire.cta.shared::cta.b64 P1, [%0], %1, 0x989680;\n\t"
            "@P1 bra.uni WD_%=;\n\t"
            "bra.uni WL_%=;\n\t"
            "WD_%=:\n\t}" :: "r"(m), "r"(parity) : "memory");
    }
}

#define LDSM4(r, a) \
    asm volatile("ldmatrix.sync.aligned.m8n8.x4.shared.b16 {%0,%1,%2,%3},[%4];" \
        : "=r"((r)[0]),"=r"((r)[1]),"=r"((r)[2]),"=r"((r)[3]) : "r"(a))
#define LDSM2(r, a) \
    asm volatile("ldmatrix.sync.aligned.m8n8.x2.shared.b16 {%0,%1},[%2];" \
        : "=r"((r)[0]),"=r"((r)[1]) : "r"(a))
#define MMA16816(d, a, b) \
    asm volatile("mma.sync.aligned.m16n8k16.row.col.f32.bf16.bf16.f32 " \
        "{%0,%1,%2,%3},{%4,%5,%6,%7},{%8,%9},{%0,%1,%2,%3};" \
        : "+f"((d)[0]),"+f"((d)[1]),"+f"((d)[2]),"+f"((d)[3]) \
        : "r"((a)[0]),"r"((a)[1]),"r"((a)[2]),"r"((a)[3]),"r"((b)[0]),"r"((b)[1]))

__device__ __forceinline__ float sigmoidf_(float x) { return 1.f / (1.f + expf(-x)); }

// ---------------- smem layout (bytes) ----------------
// Phase 0 (init): bias/mbars @0..1024, ws_hi @1024, ws_lo @67072 (ends 133120)
// Phase 1 (steady, overlays ws): ring 8x16384 @1024 (ends 132096),
//                                zpart 4x64x144B @132096 (ends 168960)
#define BS_OFF     0
#define MB_FULL    128          // 8 x 8B
#define MB_EMPTY   192          // 8 x 8B
#define WS_HI      1024
#define WS_LO      67072
#define WS_STRIDE  2064
#define RING_OFF   1024
#define A_BUF      16384
#define A_LOH      8192
#define ZP_OFF     132096
#define ZP_KG      9216         // 64 rows * 144B
#define ZP_ROW     144
#define SMEM_TOTAL 168960

// ---------------- prologue kernels ----------------
__global__ void init_kernel() {
    int idx = blockIdx.x * blockDim.x + threadIdx.x;
    int stride = gridDim.x * blockDim.x;
    int* hh = (int*)g_hs_hi;
    int* hl = (int*)g_hs_lo;
    for (int i = idx; i < (2 * 2 * 8 * 8192) / 4; i += stride) { hh[i] = 0; hl[i] = 0; }
    if (idx < NCTA) g_flags[idx] = 0u;
    if (idx == 0)   g_release   = 0u;
}

__global__ void prep_w(const float* __restrict__ Wk, const float* __restrict__ Rk) {
    __shared__ float tile[32][33];
    int gt = blockIdx.x * 32, kt = blockIdx.y * 32;
    int tid = threadIdx.x;
    for (int i = tid; i < 1024; i += PTPB) {
        int kk = i >> 5, gg = i & 31;
        int k = kt + kk, g = gt + gg;
        tile[kk][gg] = (k < 512) ? Wk[(size_t)k * 2048 + g]
                                 : Rk[(size_t)(k - 512) * 2048 + g];
    }
    __syncthreads();
    for (int i = tid; i < 1024; i += PTPB) {
        int gg = i >> 5, kk = i & 31;
        float v = tile[kk][gg];
        __nv_bfloat16 hi = __float2bfloat16(v);
        __nv_bfloat16 lo = __float2bfloat16(v - __bfloat162float(hi));
        size_t o = (size_t)(gt + gg) * 1024 + (size_t)(kt + kk);
        g_w_hi[o] = hi; g_w_lo[o] = lo;
    }
}

__global__ void prep_x(const float* __restrict__ x) {
    int t = blockIdx.x, b = blockIdx.y;
    int bg = b >> 6, r = b & 63;
    const float* src = x + ((size_t)b * Tlen + t) * Isz;
    size_t tbase = (((size_t)t * 2 + bg) * 8) * 8192;
    for (int k = threadIdx.x; k < Isz; k += blockDim.x) {
        float v = src[k];
        __nv_bfloat16 hi = __float2bfloat16(v);
        __nv_bfloat16 lo = __float2bfloat16(v - __bfloat162float(hi));
        int kt = k >> 6, kk = k & 63;
        size_t off = tbase + (size_t)kt * 8192 + r * 128 + (((kk * 2) ^ ((r & 7) << 4)));
        *(__nv_bfloat16*)(g_xs_hi + off) = hi;
        *(__nv_bfloat16*)(g_xs_lo + off) = lo;
    }
}

// ---------------- main persistent kernel ----------------
__global__ void __launch_bounds__(TPB, 1) lstm_mma(const float* __restrict__ bias,
                                                   float* __restrict__ out) {
    extern __shared__ char smem[];
    const uint32_t sbase = smem_u32(smem);
    float* bs = (float*)(smem + BS_OFF);

    const int tid = threadIdx.x, wid = tid >> 5, lid = tid & 31;
    const int cta = blockIdx.x;
    const int cg  = cta & 63;        // 8 h-cols
    const int bg  = cta >> 6;        // 64 batch rows
    const int kg  = wid >> 1;        // K-group: owns tiles kt ≡ kg (mod 4)
    const int ng  = wid & 1;         // N-group (16 n-cols)

    // ---- phase 0: weights into smem (transient) ----
    for (int i = tid; i < 32 * 128 * 2; i += TPB) {
        int half = i >= 32 * 128;
        int j = half ? i - 32 * 128 : i;
        int c = j >> 7, ch = j & 127;
        int g = (c & 3) * 512 + cg * 8 + (c >> 2);
        const __nv_bfloat16* src = (half ? g_w_lo : g_w_hi) + (size_t)g * 1024 + ch * 8;
        cpa16(sbase + (half ? WS_LO : WS_HI) + c * WS_STRIDE + ch * 16, src);
    }
    CP_COMMIT();
    if (tid < 32)
        bs[tid] = bias[(tid & 3) * 512 + cg * 8 + (tid >> 2)];
    if (tid == 0) {
        #pragma unroll
        for (int s = 0; s < NSTG; s++) {
            mbar_init(sbase + MB_FULL  + s * 8, 1);
            mbar_init(sbase + MB_EMPTY + s * 8, 2);
        }
    }
    CP_WAIT(0);
    __syncthreads();

    // ---- extract this warp's B fragments (tiles kt = kg + 4i), held forever ----
    uint32_t Bh[16][2][2], Bl[16][2][2];
    if (wid < 8) {
        #pragma unroll
        for (int kc = 0; kc < 16; kc++) {           // kc = i*4 + ks
            const uint32_t koff = kg * 128 + (kc >> 2) * 512 + (kc & 3) * 32;
            #pragma unroll
            for (int nt = 0; nt < 2; nt++) {
                uint32_t a = sbase + WS_HI
                           + (ng * 16 + nt * 8 + (lid & 7)) * WS_STRIDE
                           + ((lid >> 3) & 1) * 16 + koff;
                LDSM2(Bh[kc][nt], a);
                LDSM2(Bl[kc][nt], a + (WS_LO - WS_HI));
            }
        }
    }
    __syncthreads();   // ws region dead; ring/zpart overlay it

    // stage map: s = (kt&3)*2 + ((kt>>2)&1);  u = 2t + (kt>>3)
    auto issue_tile = [&](int t, int kt) {
        const int s = ((kt & 3) << 1) | ((kt >> 2) & 1);
        const int u = t * 2 + (kt >> 3);
        mbar_wait(sbase + MB_EMPTY + s * 8, (u & 1) ^ 1);
        const char *sh, *sl;
        if (kt < 8) {
            size_t o = (((size_t)t * 2 + bg) * 8 + kt) * 8192;
            sh = g_xs_hi + o; sl = g_xs_lo + o;
        } else {
            size_t o = (((size_t)(t & 1) * 2 + bg) * 8 + (kt - 8)) * 8192;
            sh = g_hs_hi + o; sl = g_hs_lo + o;
        }
        const uint32_t abuf = sbase + RING_OFF + s * A_BUF;
        mbar_expect(sbase + MB_FULL + s * 8, 16384);
        bulk_ld(abuf,         sh, 8192, sbase + MB_FULL + s * 8);
        bulk_ld(abuf + A_LOH, sl, 8192, sbase + MB_FULL + s * 8);
    };

    // prime: all x tiles of step 0 (fills all 8 stages)
    if (wid == 8 && lid == 0)
        for (int kt = 0; kt < 8; kt++) issue_tile(0, kt);

    // compute-warp A addressing
    const uint32_t a_row   = (lid & 15) * 128;
    const uint32_t a_cmask = (lid & 7) << 4;
    const uint32_t a_chi   = (lid >> 4) * 16;

    float creg[2] = {0.f, 0.f};

    for (int t = 0; t < Tlen; t++) {
        if (wid == 8) {
            // ---------------- producer warp ----------------
            if (lid == 0) {
                if (t > 0) {
                    while (g_release < (unsigned)t) { }
                    __threadfence();
                }
                for (int kt = 8; kt < NKT; kt++) issue_tile(t, kt);     // h tiles
                if (t + 1 < Tlen)
                    for (int kt = 0; kt < 8; kt++) issue_tile(t + 1, kt); // next x
            }
        } else {
            // ---------------- compute warps: tiles kt = kg + 4i ----------------
            float acc[4][2][4];
            #pragma unroll
            for (int mt = 0; mt < 4; mt++)
                #pragma unroll
                for (int nt = 0; nt < 2; nt++)
                    #pragma unroll
                    for (int j = 0; j < 4; j++) acc[mt][nt][j] = 0.f;

            #pragma unroll
            for (int i = 0; i < 4; i++) {
                const int s = (kg << 1) | (i & 1);
                const int u = t * 2 + (i >> 1);
                mbar_wait(sbase + MB_FULL + s * 8, u & 1);

                const uint32_t abuf = sbase + RING_OFF + s * A_BUF;
                #pragma unroll
                for (int ks = 0; ks < 4; ks++) {
                    const uint32_t col = ((uint32_t)(ks * 32) + a_chi) ^ a_cmask;
                    #pragma unroll
                    for (int mt = 0; mt < 4; mt++) {
                        uint32_t ah[4], al[4];
                        LDSM4(ah, abuf + mt * 2048 + a_row + col);
                        LDSM4(al, abuf + A_LOH + mt * 2048 + a_row + col);
                        #pragma unroll
                        for (int nt = 0; nt < 2; nt++) {
                            MMA16816(acc[mt][nt], ah, Bh[i * 4 + ks][nt]);
                            MMA16816(acc[mt][nt], ah, Bl[i * 4 + ks][nt]);
                            MMA16816(acc[mt][nt], al, Bh[i * 4 + ks][nt]);
                        }
                    }
                }
                if (lid == 0) mbar_arrive(sbase + MB_EMPTY + s * 8);
            }

            // store fp32 partials to zpart[kg]
            #pragma unroll
            for (int mt = 0; mt < 4; mt++) {
                #pragma unroll
                for (int nt = 0; nt < 2; nt++) {
                    const int r0 = mt * 16 + (lid >> 2);
                    const int c0 = ng * 16 + nt * 8 + (lid & 3) * 2;
                    char* base = smem + ZP_OFF + kg * ZP_KG + c0 * 4;
                    *(float2*)(base + r0 * ZP_ROW) =
                        make_float2(acc[mt][nt][0], acc[mt][nt][1]);
                    *(float2*)(base + (r0 + 8) * ZP_ROW) =
                        make_float2(acc[mt][nt][2], acc[mt][nt][3]);
                }
            }
        }

        __syncthreads();    // partials visible

        // ---- reduce across K-groups + gates (compute threads, 2 elems each) ----
        if (wid < 8) {
            const int par2 = (t + 1) & 1;
            #pragma unroll
            for (int e = 0; e < 2; e++) {
                const int el = tid * 2 + e;          // 0..511
                const int b  = el >> 3;              // 0..63
                const int hc = el & 7;               // 0..7
                float4 z = make_float4(0.f, 0.f, 0.f, 0.f);
                #pragma unroll
                for (int k4 = 0; k4 < 4; k4++) {
                    float4 p = *(const float4*)(smem + ZP_OFF + k4 * ZP_KG
                                                + b * ZP_ROW + hc * 16);
                    z.x += p.x; z.y += p.y; z.z += p.z; z.w += p.w;
                }
                float zi = z.x + bs[hc * 4 + 0];
                float zf = z.y + bs[hc * 4 + 1];
                float zg = z.z + bs[hc * 4 + 2];
                float zo = z.w + bs[hc * 4 + 3];
                float ii = sigmoidf_(zi);
                float ff = sigmoidf_(zf);
                float gg = tanhf(zg);
                float oo = sigmoidf_(zo);
                float cn = tanhf(ff * creg[e] + ii * gg);
                float hn = oo * cn;
                creg[e] = cn;

                const int b_glob = bg * 64 + b;
                const int hcol   = cg * 8 + hc;
                out[(size_t)b_glob * (Tlen * Hsz) + (size_t)t * Hsz + hcol] = hn;

                __nv_bfloat16 hh = __float2bfloat16(hn);
                size_t off = (((size_t)par2 * 2 + bg) * 8 + (hcol >> 6)) * 8192
                           + b * 128 + ((((hcol & 63) * 2) ^ ((b & 7) << 4)));
                *(__nv_bfloat16*)(g_hs_hi + off) = hh;
                *(__nv_bfloat16*)(g_hs_lo + off) =
                    __float2bfloat16(hn - __bfloat162float(hh));
            }
            __threadfence();
        }

        __syncthreads();    // h published

        // ---- grid barrier (producer warp only) ----
        if (t < Tlen - 1 && wid == 8) {
            unsigned gen = (unsigned)(t + 1);
            if (cta == 0) {
                if (lid == 0) g_flags[0] = gen;
                bool done;
                do {
                    done = true;
                    #pragma unroll
                    for (int j = 0; j < NCTA / 32; j++)
                        if (g_flags[lid + 32 * j] < gen) done = false;
                } while (!__all_sync(0xffffffffu, done));
                if (lid == 0) { __threadfence(); g_release = gen; }
            } else if (lid == 0) {
                g_flags[cta] = gen;
            }
        }
    }
}

// ---------------- launch ----------------
extern "C" void kernel_launch(void* const* d_in, const int* in_sizes, int n_in,
                              void* d_out, int out_size) {
    const float* x    = (const float*)d_in[0];
    const float* Wk   = (const float*)d_in[1];
    const float* Rk   = (const float*)d_in[2];
    const float* bias = (const float*)d_in[3];
    float* out = (float*)d_out;

    cudaFuncSetAttribute(lstm_mma, cudaFuncAttributeMaxDynamicSharedMemorySize, SMEM_TOTAL);

    init_kernel<<<64, PTPB>>>();
    prep_w<<<dim3(64, 32), PTPB>>>(Wk, Rk);
    prep_x<<<dim3(Tlen, Bsz), 128>>>(x);
    lstm_mma<<<NCTA, TPB, SMEM_TOTAL>>>(bias, out);
}